// round 6
// baseline (speedup 1.0000x reference)
#include <cuda_runtime.h>
#include <cuda_bf16.h>
#include <cstdint>
#include <cstddef>

// Problem constants
#define NB 16
#define NT 1024
#define ND 256
// DS = 4

#define BM 128
#define BN 128
#define LDSX 264     // bf16 elems per A/B smem row (528B, odd 16B stride -> conflict-free ldmatrix)
#define WSTRIDE 132  // fp32 elems per W smem row (528B)

#define A_OFF 0
#define B_OFF (128 * LDSX * 2)              // 67584
#define W_OFF (2 * 128 * LDSX * 2)          // 135168
#define SMEM_BYTES (W_OFF + 128 * WSTRIDE * 4)  // 202752 (~198 KB)

#define NTILE_S (NT / BN)   // 8
#define NTILE_T (NT / BM)   // 8
#define NPART (NB * NTILE_T * NTILE_S)  // 1024

#define THREADS 512   // warps 0-7: GEMM, warps 8-15: stream

// Scratch (no allocations allowed -> __device__ globals)
__device__ __align__(16) __nv_bfloat16 g_zbf[NB * NT * ND];  // 8.4 MB
__device__ float  g_z2[NB * NT];
__device__ double g_partial[NPART];

// ---------------------------------------------------------------------------
// Kernel 0: z -> bf16 copy + per-row sum of squares (z2)
// ---------------------------------------------------------------------------
__global__ void prep_kernel(const float* __restrict__ z) {
    const int warp = blockIdx.x * 8 + (threadIdx.x >> 5);
    const int lane = threadIdx.x & 31;
    const int row0 = warp * 2;

    const float4* zr0 = reinterpret_cast<const float4*>(z) + (size_t)row0 * (ND / 4);
    const float4* zr1 = zr0 + (ND / 4);
    float4 a0 = zr0[lane];
    float4 a1 = zr0[lane + 32];
    float4 b0 = zr1[lane];
    float4 b1 = zr1[lane + 32];

    float s0 = a0.x*a0.x + a0.y*a0.y + a0.z*a0.z + a0.w*a0.w
             + a1.x*a1.x + a1.y*a1.y + a1.z*a1.z + a1.w*a1.w;
    float s1 = b0.x*b0.x + b0.y*b0.y + b0.z*b0.z + b0.w*b0.w
             + b1.x*b1.x + b1.y*b1.y + b1.z*b1.z + b1.w*b1.w;
    #pragma unroll
    for (int o = 16; o; o >>= 1) {
        s0 += __shfl_xor_sync(0xffffffffu, s0, o);
        s1 += __shfl_xor_sync(0xffffffffu, s1, o);
    }
    if (lane == 0) { g_z2[row0] = s0; g_z2[row0 + 1] = s1; }

    uint2* d0 = reinterpret_cast<uint2*>(g_zbf + (size_t)row0 * ND);
    uint2* d1 = d0 + (ND / 4);   // one row = ND/4 uint2
    auto pack = [](float4 v) {
        __nv_bfloat162 lo = __floats2bfloat162_rn(v.x, v.y);
        __nv_bfloat162 hi = __floats2bfloat162_rn(v.z, v.w);
        uint2 p;
        p.x = *reinterpret_cast<uint32_t*>(&lo);
        p.y = *reinterpret_cast<uint32_t*>(&hi);
        return p;
    };
    d0[lane]      = pack(a0);
    d0[lane + 32] = pack(a1);
    d1[lane]      = pack(b0);
    d1[lane + 32] = pack(b1);
}

// ---------------------------------------------------------------------------
// Main fused kernel — WARP SPECIALIZED:
//   warps 0-7 : G = Zt * Zs^T (mma.sync, regs)         } run concurrently
//   warps 8-15: stream gt, w=exp(...) -> smem W,       } on the same SM
//               accumulate z2[t]*sum(w)
//   then one sync; GEMM warps combine -sum(w*G); 16-warp reduction.
// ---------------------------------------------------------------------------
#define LDSM4(r0, r1, r2, r3, addr)                                              \
    asm volatile("ldmatrix.sync.aligned.m8n8.x4.shared.b16 {%0,%1,%2,%3}, [%4];" \
                 : "=r"(r0), "=r"(r1), "=r"(r2), "=r"(r3) : "r"(addr))

#define MMA16816(d, a, b0r, b1r)                                                 \
    asm volatile("mma.sync.aligned.m16n8k16.row.col.f32.bf16.bf16.f32 "          \
                 "{%0,%1,%2,%3}, {%4,%5,%6,%7}, {%8,%9}, {%0,%1,%2,%3};"         \
                 : "+f"(d[0]), "+f"(d[1]), "+f"(d[2]), "+f"(d[3])                \
                 : "r"(a[0]), "r"(a[1]), "r"(a[2]), "r"(a[3]), "r"(b0r), "r"(b1r))

__global__ void __launch_bounds__(THREADS, 1)
main_kernel(const float* __restrict__ gt, const float* __restrict__ sigma) {
    extern __shared__ __align__(16) char sm[];
    __nv_bfloat16* As = reinterpret_cast<__nv_bfloat16*>(sm + A_OFF);
    __nv_bfloat16* Bs = reinterpret_cast<__nv_bfloat16*>(sm + B_OFF);
    float* Ws = reinterpret_cast<float*>(sm + W_OFF);

    const int bb = blockIdx.z;
    const int t0 = blockIdx.y * BM;
    const int sB = blockIdx.x * BN;
    const int tid = threadIdx.x;
    const int lane = tid & 31;
    const int wid  = tid >> 5;

    // ---- all 512 threads: load Zt / Zs tiles into smem ----
    {
        const int4* gzt = reinterpret_cast<const int4*>(g_zbf + ((size_t)bb * NT + t0) * ND);
        const int4* gzs = reinterpret_cast<const int4*>(g_zbf + ((size_t)bb * NT + sB) * ND);
        #pragma unroll
        for (int i = 0; i < 8; i++) {
            int idx = tid + i * 512;           // 0..4095 : 128 rows x 32 int4
            int r = idx >> 5, c = idx & 31;
            *reinterpret_cast<int4*>(As + r * LDSX + c * 8) = gzt[idx];
            *reinterpret_cast<int4*>(Bs + r * LDSX + c * 8) = gzs[idx];
        }
    }
    __syncthreads();

    float part = 0.f;

    if (wid < 8) {
        // ================= GEMM warps =================
        const int wm = (wid & 3) * 32;   // rows 0,32,64,96
        const int wn = (wid >> 2) * 64;  // cols 0,64

        float acc[2][8][4];
        #pragma unroll
        for (int mi = 0; mi < 2; mi++)
            #pragma unroll
            for (int ni = 0; ni < 8; ni++)
                #pragma unroll
                for (int r = 0; r < 4; r++) acc[mi][ni][r] = 0.f;

        const uint32_t aBase = (uint32_t)__cvta_generic_to_shared(As);
        const uint32_t bBase = (uint32_t)__cvta_generic_to_shared(Bs);
        const uint32_t aAddr0 = aBase + (((wm + (lane & 15)) * LDSX + (lane >> 4) * 8)) * 2;
        const uint32_t bAddr0 = bBase + (((wn + (lane & 7) + ((lane >> 4) << 3)) * LDSX
                                         + ((lane >> 3) & 1) * 8)) * 2;

        #pragma unroll
        for (int kk = 0; kk < 16; kk++) {
            uint32_t a[2][4];
            #pragma unroll
            for (int mi = 0; mi < 2; mi++) {
                uint32_t addr = aAddr0 + (uint32_t)(mi * 16 * LDSX * 2) + (uint32_t)(kk * 32);
                LDSM4(a[mi][0], a[mi][1], a[mi][2], a[mi][3], addr);
            }
            uint32_t bf[8][2];
            #pragma unroll
            for (int nj = 0; nj < 4; nj++) {
                uint32_t addr = bAddr0 + (uint32_t)(nj * 16 * LDSX * 2) + (uint32_t)(kk * 32);
                uint32_t r0, r1, r2, r3;
                LDSM4(r0, r1, r2, r3, addr);
                bf[2 * nj][0] = r0;     bf[2 * nj][1] = r1;
                bf[2 * nj + 1][0] = r2; bf[2 * nj + 1][1] = r3;
            }
            #pragma unroll
            for (int mi = 0; mi < 2; mi++)
                #pragma unroll
                for (int ni = 0; ni < 8; ni++)
                    MMA16816(acc[mi][ni], a[mi], bf[ni][0], bf[ni][1]);
        }

        __syncthreads();   // wait for stream warps to fill W

        // ---- combine: part = -sum(w * G) over this warp's fragment ----
        const int rowc = lane >> 2;          // 0..7
        const int colc = (lane & 3) * 2;     // 0,2,4,6
        float p2 = 0.f;
        #pragma unroll
        for (int mi = 0; mi < 2; mi++) {
            #pragma unroll
            for (int h = 0; h < 2; h++) {
                const int row = wm + mi * 16 + rowc + h * 8;
                const float* wr = Ws + row * WSTRIDE + wn + colc;
                #pragma unroll
                for (int ni = 0; ni < 8; ni++) {
                    float2 wv = *reinterpret_cast<const float2*>(wr + ni * 8);
                    p2 += wv.x * acc[mi][ni][h * 2 + 0];
                    p2 += wv.y * acc[mi][ni][h * 2 + 1];
                }
            }
        }
        part = -p2;
    } else {
        // ================= Stream warps =================
        const float sg0 = sigma[0], sg1 = sigma[1], sg2 = sigma[2], sg3 = sigma[3];
        const float inv0 = 1.0f / (2.0f * sg0 * sg0);
        const float inv1 = 1.0f / (2.0f * sg1 * sg1);
        const float inv2 = 1.0f / (2.0f * sg2 * sg2);
        const float inv3 = 1.0f / (2.0f * sg3 * sg3);

        const int st   = (wid - 8) * 32 + lane;   // 0..255
        const int row  = st & 127;                // gt/W row within tile
        const int cbase = (st >> 7) * 64;         // 0 or 64

        const float4* gp = reinterpret_cast<const float4*>(gt)
                         + ((size_t)bb * NT + (t0 + row)) * NT + (sB + cbase);
        float* wrow = Ws + row * WSTRIDE + cbase;

        float sumw = 0.f;
        #pragma unroll
        for (int c = 0; c < 8; c++) {
            float4 g[8];
            #pragma unroll
            for (int j = 0; j < 8; j++) g[j] = __ldcs(gp + c * 8 + j);
            float w[8];
            #pragma unroll
            for (int j = 0; j < 8; j++) {
                float q = g[j].x * g[j].x * inv0 + g[j].y * g[j].y * inv1
                        + g[j].z * g[j].z * inv2 + g[j].w * g[j].w * inv3;
                w[j] = __expf(q);
                sumw += w[j];
            }
            *reinterpret_cast<float4*>(wrow + c * 8)     = make_float4(w[0], w[1], w[2], w[3]);
            *reinterpret_cast<float4*>(wrow + c * 8 + 4) = make_float4(w[4], w[5], w[6], w[7]);
        }

        part = g_z2[bb * NT + t0 + row] * sumw;
        __syncthreads();   // publish W to GEMM warps
    }

    // ---- CTA reduction (deterministic, 16 warps) ----
    #pragma unroll
    for (int o = 16; o; o >>= 1) part += __shfl_xor_sync(0xffffffffu, part, o);
    __shared__ double red[16];
    if (lane == 0) red[wid] = (double)part;
    __syncthreads();
    if (tid == 0) {
        double ssum = 0.0;
        #pragma unroll
        for (int i = 0; i < 16; i++) ssum += red[i];
        g_partial[(blockIdx.z * NTILE_T + blockIdx.y) * NTILE_S + blockIdx.x] = ssum;
    }
}

// ---------------------------------------------------------------------------
// Finalize: fixed-order tree reduction of partials -> scalar loss
// ---------------------------------------------------------------------------
__global__ void finalize_kernel(float* __restrict__ out) {
    __shared__ double red[256];
    double v = 0.0;
    for (int i = threadIdx.x; i < NPART; i += 256) v += g_partial[i];
    red[threadIdx.x] = v;
    __syncthreads();
    for (int off = 128; off; off >>= 1) {
        if (threadIdx.x < off) red[threadIdx.x] += red[threadIdx.x + off];
        __syncthreads();
    }
    if (threadIdx.x == 0)
        out[0] = (float)(red[0] * (2.0 / ((double)NB * (double)NT * (double)NT)));
}

// ---------------------------------------------------------------------------
extern "C" void kernel_launch(void* const* d_in, const int* in_sizes, int n_in,
                              void* d_out, int out_size) {
    const float* z     = (const float*)d_in[0];  // [16,1024,256]
    const float* gt    = (const float*)d_in[1];  // [16,1024,1024,4]
    const float* sigma = (const float*)d_in[2];  // [4]
    float* out = (float*)d_out;

    cudaFuncSetAttribute(main_kernel, cudaFuncAttributeMaxDynamicSharedMemorySize, SMEM_BYTES);

    prep_kernel<<<NB * NT / 16, 256>>>(z);
    main_kernel<<<dim3(NTILE_S, NTILE_T, NB), THREADS, SMEM_BYTES>>>(gt, sigma);
    finalize_kernel<<<1, 256>>>(out);
}

// round 7
// speedup vs baseline: 1.3828x; 1.3828x over previous
#include <cuda_runtime.h>
#include <cuda_bf16.h>
#include <cstdint>
#include <cstddef>

// Problem constants
#define NB 16
#define NT 1024
#define ND 256
// DS = 4

#define BM 128
#define LDSX 264   // bf16 elems per A/B smem row (528B, odd 16B stride -> conflict-free ldmatrix)
#define LDSG 129   // fp32 elems per G smem row (odd word stride -> conflict-free rows AND cols)

#define A_OFF 0
#define B_OFF (128 * LDSX * 2)              // 67584
#define SMEM_BYTES (2 * 128 * LDSX * 2)     // 135168 (~132 KB); G (128*129*4=66048) overlays A

#define NTILE (NT / BM)                 // 8
#define NPAIR (NTILE * (NTILE + 1) / 2) // 36
#define NPART (NB * NPAIR)              // 576

// Scratch (no allocations allowed -> __device__ globals)
__device__ __align__(16) __nv_bfloat16 g_zbf[NB * NT * ND];  // 8.4 MB
__device__ float  g_z2[NB * NT];
__device__ double g_partial[NPART];

// pair p -> (i,j), i<=j, over 8 tiles
__constant__ int PAIR_I[NPAIR] = {0,0,0,0,0,0,0,0, 1,1,1,1,1,1,1, 2,2,2,2,2,2,
                                  3,3,3,3,3, 4,4,4,4, 5,5,5, 6,6, 7};
__constant__ int PAIR_J[NPAIR] = {0,1,2,3,4,5,6,7, 1,2,3,4,5,6,7, 2,3,4,5,6,7,
                                  3,4,5,6,7, 4,5,6,7, 5,6,7, 6,7, 7};

// ---------------------------------------------------------------------------
// Kernel 0: z -> bf16 copy + per-row sum of squares (z2)
// ---------------------------------------------------------------------------
__global__ void prep_kernel(const float* __restrict__ z) {
    const int warp = blockIdx.x * 8 + (threadIdx.x >> 5);
    const int lane = threadIdx.x & 31;
    const int row0 = warp * 2;

    const float4* zr0 = reinterpret_cast<const float4*>(z) + (size_t)row0 * (ND / 4);
    const float4* zr1 = zr0 + (ND / 4);
    float4 a0 = zr0[lane];
    float4 a1 = zr0[lane + 32];
    float4 b0 = zr1[lane];
    float4 b1 = zr1[lane + 32];

    float s0 = a0.x*a0.x + a0.y*a0.y + a0.z*a0.z + a0.w*a0.w
             + a1.x*a1.x + a1.y*a1.y + a1.z*a1.z + a1.w*a1.w;
    float s1 = b0.x*b0.x + b0.y*b0.y + b0.z*b0.z + b0.w*b0.w
             + b1.x*b1.x + b1.y*b1.y + b1.z*b1.z + b1.w*b1.w;
    #pragma unroll
    for (int o = 16; o; o >>= 1) {
        s0 += __shfl_xor_sync(0xffffffffu, s0, o);
        s1 += __shfl_xor_sync(0xffffffffu, s1, o);
    }
    if (lane == 0) { g_z2[row0] = s0; g_z2[row0 + 1] = s1; }

    uint2* d0 = reinterpret_cast<uint2*>(g_zbf + (size_t)row0 * ND);
    uint2* d1 = d0 + (ND / 4);
    auto pack = [](float4 v) {
        __nv_bfloat162 lo = __floats2bfloat162_rn(v.x, v.y);
        __nv_bfloat162 hi = __floats2bfloat162_rn(v.z, v.w);
        uint2 p;
        p.x = *reinterpret_cast<uint32_t*>(&lo);
        p.y = *reinterpret_cast<uint32_t*>(&hi);
        return p;
    };
    d0[lane]      = pack(a0);
    d0[lane + 32] = pack(a1);
    d1[lane]      = pack(b0);
    d1[lane + 32] = pack(b1);
}

// ---------------------------------------------------------------------------
// Main kernel, one CTA per (batch, tile-pair (i<=j)):
//   1. GEMM G = Z_i * Z_j^T  (mma.sync, 256 thr, regs — proven R1 code)
//   2. stage G into smem [128][129] fp32 (overlays A tile)
//   3. stream gt tile (i,j):   part += w * (z2[i-row] - G[row][col])
//   4. if i!=j, stream (j,i):  part += w * (z2[j-row] - G[col][row])
// Symmetry halves total GEMM work vs one-CTA-per-tile.
// ---------------------------------------------------------------------------
#define LDSM4(r0, r1, r2, r3, addr)                                              \
    asm volatile("ldmatrix.sync.aligned.m8n8.x4.shared.b16 {%0,%1,%2,%3}, [%4];" \
                 : "=r"(r0), "=r"(r1), "=r"(r2), "=r"(r3) : "r"(addr))

#define MMA16816(d, a, b0r, b1r)                                                 \
    asm volatile("mma.sync.aligned.m16n8k16.row.col.f32.bf16.bf16.f32 "          \
                 "{%0,%1,%2,%3}, {%4,%5,%6,%7}, {%8,%9}, {%0,%1,%2,%3};"         \
                 : "+f"(d[0]), "+f"(d[1]), "+f"(d[2]), "+f"(d[3])                \
                 : "r"(a[0]), "r"(a[1]), "r"(a[2]), "r"(a[3]), "r"(b0r), "r"(b1r))

__global__ void __launch_bounds__(256, 1)
main_kernel(const float* __restrict__ gt, const float* __restrict__ sigma) {
    extern __shared__ __align__(16) char sm[];
    __nv_bfloat16* As = reinterpret_cast<__nv_bfloat16*>(sm + A_OFF);
    __nv_bfloat16* Bs = reinterpret_cast<__nv_bfloat16*>(sm + B_OFF);
    float* Gs = reinterpret_cast<float*>(sm + A_OFF);   // overlays A after GEMM

    const int bb = blockIdx.z;
    const int ti = PAIR_I[blockIdx.x];
    const int tj = PAIR_J[blockIdx.x];
    const int tid = threadIdx.x;
    const int lane = tid & 31;
    const int wid  = tid >> 5;

    // ---- load Z_i / Z_j tiles into smem ----
    {
        const int4* gzt = reinterpret_cast<const int4*>(g_zbf + ((size_t)bb * NT + ti * BM) * ND);
        const int4* gzs = reinterpret_cast<const int4*>(g_zbf + ((size_t)bb * NT + tj * BM) * ND);
        #pragma unroll
        for (int i = 0; i < 16; i++) {
            int idx = tid + i * 256;           // 0..4095 : 128 rows x 32 int4
            int r = idx >> 5, c = idx & 31;
            *reinterpret_cast<int4*>(As + r * LDSX + c * 8) = gzt[idx];
            *reinterpret_cast<int4*>(Bs + r * LDSX + c * 8) = gzs[idx];
        }
    }
    __syncthreads();

    // ---- GEMM (R1-proven): warp = 32 rows x 64 cols ----
    const int wm = (wid & 3) * 32;
    const int wn = (wid >> 2) * 64;

    float acc[2][8][4];
    #pragma unroll
    for (int mi = 0; mi < 2; mi++)
        #pragma unroll
        for (int ni = 0; ni < 8; ni++)
            #pragma unroll
            for (int r = 0; r < 4; r++) acc[mi][ni][r] = 0.f;

    const uint32_t aBase = (uint32_t)__cvta_generic_to_shared(As);
    const uint32_t bBase = (uint32_t)__cvta_generic_to_shared(Bs);
    const uint32_t aAddr0 = aBase + (((wm + (lane & 15)) * LDSX + (lane >> 4) * 8)) * 2;
    const uint32_t bAddr0 = bBase + (((wn + (lane & 7) + ((lane >> 4) << 3)) * LDSX
                                     + ((lane >> 3) & 1) * 8)) * 2;

    #pragma unroll
    for (int kk = 0; kk < 16; kk++) {
        uint32_t a[2][4];
        #pragma unroll
        for (int mi = 0; mi < 2; mi++) {
            uint32_t addr = aAddr0 + (uint32_t)(mi * 16 * LDSX * 2) + (uint32_t)(kk * 32);
            LDSM4(a[mi][0], a[mi][1], a[mi][2], a[mi][3], addr);
        }
        uint32_t bf[8][2];
        #pragma unroll
        for (int nj = 0; nj < 4; nj++) {
            uint32_t addr = bAddr0 + (uint32_t)(nj * 16 * LDSX * 2) + (uint32_t)(kk * 32);
            uint32_t r0, r1, r2, r3;
            LDSM4(r0, r1, r2, r3, addr);
            bf[2 * nj][0] = r0;     bf[2 * nj][1] = r1;
            bf[2 * nj + 1][0] = r2; bf[2 * nj + 1][1] = r3;
        }
        #pragma unroll
        for (int mi = 0; mi < 2; mi++)
            #pragma unroll
            for (int ni = 0; ni < 8; ni++)
                MMA16816(acc[mi][ni], a[mi], bf[ni][0], bf[ni][1]);
    }

    __syncthreads();   // everyone done reading A/B

    // ---- stage G into smem [128][LDSG] fp32 ----
    {
        const int rowc = lane >> 2;
        const int colc = (lane & 3) * 2;
        #pragma unroll
        for (int mi = 0; mi < 2; mi++)
            #pragma unroll
            for (int h = 0; h < 2; h++) {
                const int row = wm + mi * 16 + rowc + h * 8;
                #pragma unroll
                for (int ni = 0; ni < 8; ni++) {
                    const int col = wn + ni * 8 + colc;
                    Gs[row * LDSG + col]     = acc[mi][ni][h * 2 + 0];
                    Gs[row * LDSG + col + 1] = acc[mi][ni][h * 2 + 1];
                }
            }
    }
    __syncthreads();

    // ---- streaming passes ----
    const float sg0 = sigma[0], sg1 = sigma[1], sg2 = sigma[2], sg3 = sigma[3];
    const float inv0 = 1.0f / (2.0f * sg0 * sg0);
    const float inv1 = 1.0f / (2.0f * sg1 * sg1);
    const float inv2 = 1.0f / (2.0f * sg2 * sg2);
    const float inv3 = 1.0f / (2.0f * sg3 * sg3);

    const int row   = tid & 127;          // row within streamed tile
    const int cbase = (tid >> 7) * 64;    // 0 or 64

    float part = 0.f;

    // pass 1: tile (ti, tj); G indexed [row][col]
    {
        const float4* gp = reinterpret_cast<const float4*>(gt)
                         + ((size_t)bb * NT + (ti * BM + row)) * NT + (tj * BM + cbase);
        const float zz = g_z2[bb * NT + ti * BM + row];
        const float* gr = Gs + row * LDSG + cbase;
        #pragma unroll
        for (int c = 0; c < 8; c++) {
            float4 g[8];
            #pragma unroll
            for (int j = 0; j < 8; j++) g[j] = __ldcs(gp + c * 8 + j);
            #pragma unroll
            for (int j = 0; j < 8; j++) {
                float q = g[j].x * g[j].x * inv0 + g[j].y * g[j].y * inv1
                        + g[j].z * g[j].z * inv2 + g[j].w * g[j].w * inv3;
                float w = __expf(q);
                part += w * (zz - gr[c * 8 + j]);
            }
        }
    }

    // pass 2: tile (tj, ti); G indexed [col][row] (transpose)
    if (ti != tj) {
        const float4* gp = reinterpret_cast<const float4*>(gt)
                         + ((size_t)bb * NT + (tj * BM + row)) * NT + (ti * BM + cbase);
        const float zz = g_z2[bb * NT + tj * BM + row];
        const float* gc = Gs + cbase * LDSG + row;
        #pragma unroll
        for (int c = 0; c < 8; c++) {
            float4 g[8];
            #pragma unroll
            for (int j = 0; j < 8; j++) g[j] = __ldcs(gp + c * 8 + j);
            #pragma unroll
            for (int j = 0; j < 8; j++) {
                float q = g[j].x * g[j].x * inv0 + g[j].y * g[j].y * inv1
                        + g[j].z * g[j].z * inv2 + g[j].w * g[j].w * inv3;
                float w = __expf(q);
                part += w * (zz - gc[(c * 8 + j) * LDSG]);
            }
        }
    }

    // ---- CTA reduction (deterministic) ----
    #pragma unroll
    for (int o = 16; o; o >>= 1) part += __shfl_xor_sync(0xffffffffu, part, o);
    __shared__ double red[8];
    if (lane == 0) red[wid] = (double)part;
    __syncthreads();
    if (tid == 0) {
        double ssum = 0.0;
        #pragma unroll
        for (int i = 0; i < 8; i++) ssum += red[i];
        g_partial[blockIdx.z * NPAIR + blockIdx.x] = ssum;
    }
}

// ---------------------------------------------------------------------------
// Finalize: fixed-order tree reduction of partials -> scalar loss
// ---------------------------------------------------------------------------
__global__ void finalize_kernel(float* __restrict__ out) {
    __shared__ double red[256];
    double v = 0.0;
    for (int i = threadIdx.x; i < NPART; i += 256) v += g_partial[i];
    red[threadIdx.x] = v;
    __syncthreads();
    for (int off = 128; off; off >>= 1) {
        if (threadIdx.x < off) red[threadIdx.x] += red[threadIdx.x + off];
        __syncthreads();
    }
    if (threadIdx.x == 0)
        out[0] = (float)(red[0] * (2.0 / ((double)NB * (double)NT * (double)NT)));
}

// ---------------------------------------------------------------------------
extern "C" void kernel_launch(void* const* d_in, const int* in_sizes, int n_in,
                              void* d_out, int out_size) {
    const float* z     = (const float*)d_in[0];  // [16,1024,256]
    const float* gt    = (const float*)d_in[1];  // [16,1024,1024,4]
    const float* sigma = (const float*)d_in[2];  // [4]
    float* out = (float*)d_out;

    cudaFuncSetAttribute(main_kernel, cudaFuncAttributeMaxDynamicSharedMemorySize, SMEM_BYTES);

    prep_kernel<<<NB * NT / 16, 256>>>(z);
    main_kernel<<<dim3(NPAIR, 1, NB), 256, SMEM_BYTES>>>(gt, sigma);
    finalize_kernel<<<1, 256>>>(out);
}